// round 1
// baseline (speedup 1.0000x reference)
#include <cuda_runtime.h>

// ConditionalSplineSQ2D: out[b] = sum_{g,h,c} param[b,g,h,ii[c]]*param[b,g,h,jj[c]]*coef[g,h,c]
// B=4096, G=31 (G*G=961 cells), P=8, C=36 (upper-tri-with-diag pairs).
//
// Design: persistent blocks (one per SM), 1024 threads. Thread t owns cell t
// (t<961) and keeps its 36 coefficients in registers (loaded once). Loop over
// b with grid stride: each thread loads its cell's 8 params (2x float4,
// perfectly coalesced: warp reads 1024 contiguous bytes), computes
//   acc = sum_i p_i * (sum_{j>=i} cf[i,j] * p_j)   (44 FMA)
// then block-reduces 961 partials into out[b]. Double-buffered reduce slots
// allow a single __syncthreads per b; next-b loads are issued before the
// barrier to overlap DRAM latency with the reduction.

#define GG    961
#define CC    36
#define NTHR  1024
#define NWARP 32

__global__ __launch_bounds__(NTHR, 1)
void sq2d_kernel(const float* __restrict__ param,
                 const float* __restrict__ coef,
                 float* __restrict__ out,
                 int nB, int stride)
{
    __shared__ float red[2][NWARP];

    const int tid  = threadIdx.x;
    const int lane = tid & 31;
    const int warp = tid >> 5;
    const bool active = (tid < GG);
    const int cell = active ? tid : (GG - 1);

    // Load this cell's 36 coefficients into registers (zero for pad threads).
    float cf[CC];
#pragma unroll
    for (int c = 0; c < CC; c++)
        cf[c] = active ? coef[cell * CC + c] : 0.0f;

    // param viewed as float4: per-b stride = 961*8 floats = 961*2 float4.
    const float4* pbase = reinterpret_cast<const float4*>(param) + (size_t)cell * 2;

    int b = blockIdx.x;
    float4 a0, a1;
    if (b < nB) {
        const float4* p = pbase + (size_t)b * (GG * 2);
        a0 = p[0];
        a1 = p[1];
    }

    int buf = 0;
    while (b < nB) {
        const int bn = b + stride;

        float pv[8] = { a0.x, a0.y, a0.z, a0.w, a1.x, a1.y, a1.z, a1.w };

        // acc = sum_{i<=j} cf[c(i,j)] * p_i * p_j, factored row-wise: 44 FMA.
        float acc = 0.0f;
        int c = 0;
#pragma unroll
        for (int i = 0; i < 8; i++) {
            float q = 0.0f;
#pragma unroll
            for (int j = i; j < 8; j++)
                q = fmaf(cf[c++], pv[j], q);
            acc = fmaf(pv[i], q, acc);
        }

        // Prefetch next b's params BEFORE the barrier so the DRAM latency
        // overlaps the block reduction + barrier.
        if (bn < nB) {
            const float4* p = pbase + (size_t)bn * (GG * 2);
            a0 = p[0];
            a1 = p[1];
        }

        // Warp reduce.
#pragma unroll
        for (int o = 16; o > 0; o >>= 1)
            acc += __shfl_xor_sync(0xffffffffu, acc, o);
        if (lane == 0) red[buf][warp] = acc;

        __syncthreads();

        if (warp == 0) {
            float v = red[buf][lane];
#pragma unroll
            for (int o = 16; o > 0; o >>= 1)
                v += __shfl_xor_sync(0xffffffffu, v, o);
            if (lane == 0) out[b] = v;
        }

        buf ^= 1;
        b = bn;
    }
}

extern "C" void kernel_launch(void* const* d_in, const int* in_sizes, int n_in,
                              void* d_out, int out_size)
{
    const float* param = (const float*)d_in[0];   // [B, 31, 31, 8] f32
    const float* coef  = (const float*)d_in[1];   // [31, 31, 36]   f32
    float* out = (float*)d_out;                    // [B] f32

    const int nB = in_sizes[0] / (GG * 8);

    int dev = 0, sms = 0;
    cudaGetDevice(&dev);
    cudaDeviceGetAttribute(&sms, cudaDevAttrMultiProcessorCount, dev);
    if (sms <= 0) sms = 148;
    if (sms > nB) sms = nB;

    sq2d_kernel<<<sms, NTHR>>>(param, coef, out, nB, sms);
}